// round 12
// baseline (speedup 1.0000x reference)
#include <cuda_runtime.h>

#define Bsz   128
#define Lseq  4096
#define Hd    64
#define G3    192
#define IN2H  128
#define NCLS  230
#define BL    (Bsz * Lseq)

typedef unsigned long long ull;

// Scratch (allocation-free rule: __device__ globals)
__device__ float g_gx[(size_t)2 * BL * G3];    // [dir][b][t][192]  (~805 MB)
__device__ float g_buf[(size_t)BL * IN2H];     // [b][t][128]       (~268 MB)

// ---------------- packed f32x2 / fast-math helpers ----------------
__device__ __forceinline__ ull fma2(ull a, ull b, ull c) {
    ull d;
    asm("fma.rn.f32x2 %0, %1, %2, %3;" : "=l"(d) : "l"(a), "l"(b), "l"(c));
    return d;
}
__device__ __forceinline__ float2 u2f2(ull v) {
    float2 f;
    asm("mov.b64 {%0, %1}, %2;" : "=f"(f.x), "=f"(f.y) : "l"(v));
    return f;
}
__device__ __forceinline__ float tanh_fast(float x) {
    float y;
    asm("tanh.approx.f32 %0, %1;" : "=f"(y) : "f"(x));
    return y;
}
__device__ __forceinline__ float sigm_fast(float x) {
    return fmaf(0.5f, tanh_fast(0.5f * x), 0.5f);
}
__device__ __forceinline__ unsigned smem_u32(const void* p) {
    return (unsigned)__cvta_generic_to_shared(p);
}
__device__ __forceinline__ void cp_async8(unsigned dst, const void* src) {
    asm volatile("cp.async.ca.shared.global [%0], [%1], 8;"
                 :: "r"(dst), "l"(src));
}
__device__ __forceinline__ void cp_commit() {
    asm volatile("cp.async.commit_group;");
}
template <int N>
__device__ __forceinline__ void cp_wait() {
    asm volatile("cp.async.wait_group %0;" :: "n"(N));
}

// ---------------- gx GEMM for layers 1..3 (frozen R7 version) -------------
__global__ void __launch_bounds__(256, 2)
gx_gemm_kernel(const float* __restrict__ w_ih,
               const float* __restrict__ b_ih,
               int layer) {
    const int d  = blockIdx.x & 1;
    const int c0 = (blockIdx.x >> 1) * 96;       // column half
    const size_t row0 = (size_t)blockIdx.y * 64;
    const int tid = threadIdx.x;
    const int tx = tid & 15;   // cols c0 + tx + 16*j, j<6
    const int ty = tid >> 4;   // rows ty + 16*i, i<4

    const ull* inp2 = (const ull*)g_buf;  // 64 ull per row
    const ull* w2g =
        (const ull*)(w_ih + ((size_t)(layer - 1) * 2 + d) * G3 * IN2H);

    __shared__ ull a_s[2][16][65];   // [buf][kpair][row]
    __shared__ ull b_s[2][16][97];   // [buf][kpair][col]
    const unsigned A_BUF_BYTES = 16 * 65 * 8;
    const unsigned B_BUF_BYTES = 16 * 97 * 8;

    unsigned a_dst[4], b_dst[6];
    const ull* a_src[4];
    const ull* b_src[6];
#pragma unroll
    for (int it = 0; it < 4; it++) {
        int lin = tid + it * 256;
        int r = lin >> 4, c2 = lin & 15;
        a_dst[it] = smem_u32(&a_s[0][c2][r]);
        a_src[it] = inp2 + (row0 + r) * 64 + c2;
    }
#pragma unroll
    for (int it = 0; it < 6; it++) {
        int lin = tid + it * 256;
        int cc = lin >> 4, c2 = lin & 15;
        b_dst[it] = smem_u32(&b_s[0][c2][cc]);
        b_src[it] = w2g + (size_t)(c0 + cc) * 64 + c2;
    }

    ull acc[4][6];
#pragma unroll
    for (int i = 0; i < 4; i++)
#pragma unroll
        for (int j = 0; j < 6; j++) acc[i][j] = 0ULL;

#pragma unroll
    for (int it = 0; it < 4; it++) cp_async8(a_dst[it], a_src[it]);
#pragma unroll
    for (int it = 0; it < 6; it++) cp_async8(b_dst[it], b_src[it]);
    cp_commit();

#pragma unroll
    for (int ch = 0; ch < 4; ch++) {
        const int buf = ch & 1;
        if (ch < 3) {
            const int nb = (ch + 1) & 1;
#pragma unroll
            for (int it = 0; it < 4; it++)
                cp_async8(a_dst[it] + nb * A_BUF_BYTES,
                          a_src[it] + (ch + 1) * 16);
#pragma unroll
            for (int it = 0; it < 6; it++)
                cp_async8(b_dst[it] + nb * B_BUF_BYTES,
                          b_src[it] + (ch + 1) * 16);
            cp_commit();
            cp_wait<1>();
        } else {
            cp_wait<0>();
        }
        __syncthreads();
#pragma unroll
        for (int kp = 0; kp < 16; kp++) {
            ull a2[4], b2[6];
#pragma unroll
            for (int i = 0; i < 4; i++) a2[i] = a_s[buf][kp][ty + 16 * i];
#pragma unroll
            for (int j = 0; j < 6; j++) b2[j] = b_s[buf][kp][tx + 16 * j];
#pragma unroll
            for (int i = 0; i < 4; i++)
#pragma unroll
                for (int j = 0; j < 6; j++)
                    acc[i][j] = fma2(a2[i], b2[j], acc[i][j]);
        }
        __syncthreads();
    }

    const float* bih = b_ih + ((size_t)layer * 2 + d) * G3;
#pragma unroll
    for (int i = 0; i < 4; i++) {
        size_t row = row0 + ty + 16 * i;
#pragma unroll
        for (int j = 0; j < 6; j++) {
            int c = c0 + tx + 16 * j;
            float2 f = u2f2(acc[i][j]);
            g_gx[((size_t)d * BL + row) * G3 + c] = f.x + f.y + bih[c];
        }
    }
}

// ---------------- sequential GRU scan (k-split=4, one sequence/block) -----
// Block = one (batch, direction) sequence, 256 threads, 2 CTAs/SM.
//   j = tid>>2 : h-component 0..63
//   q = tid&3  : 16-wide k-quarter of the dot products
// Each thread computes ALL THREE gate dots (r,z,n) for component j over its
// k-quarter (weights 3x8 ull = 48 regs). Quarters combine via shfl_xor(1)
// then shfl_xor(2) (partners are lanes j*4+q, in-warp). Gates + h update +
// gx prefetch on q==0 threads. Ping-pong h buffer, one __syncthreads/step,
// step loop unrolled x2 so parity & prefetch scalars are compile-time.
__global__ void __launch_bounds__(256, 2)
scan_kernel(const float* __restrict__ w_hh,
            const float* __restrict__ b_hh,
            const float* __restrict__ x,
            const float* __restrict__ w_ih0,
            const float* __restrict__ b_ih,
            int layer) {
    const int b = blockIdx.x;
    const int d = blockIdx.y;
    const int tid = threadIdx.x;
    const int j = tid >> 2;   // component
    const int q = tid & 3;    // k-quarter

    const size_t base = ((size_t)layer * 2 + d) * G3;
    const ull* Wr = (const ull*)w_hh + (base + j) * 32 + q * 8;
    const ull* Wz = (const ull*)w_hh + (base + 64 + j) * 32 + q * 8;
    const ull* Wn = (const ull*)w_hh + (base + 128 + j) * 32 + q * 8;
    ull wr[8], wz[8], wn[8];
#pragma unroll
    for (int i = 0; i < 8; i++) { wr[i] = Wr[i]; wz[i] = Wz[i]; wn[i] = Wn[i]; }
    const float br = b_hh[base + j];
    const float bz = b_hh[base + 64 + j];
    const float bn = b_hh[base + 128 + j];

    __shared__ __align__(16) float h_s[2][Hd];   // [parity][comp]
    if (tid < Hd) h_s[0][tid] = 0.0f;
    float hreg = 0.0f;  // previous h[j], maintained on q==0

    const int t0 = (d == 0) ? 0 : (Lseq - 1);
    const int tstep = (d == 0) ? 1 : -1;
    const long gstep = (long)tstep * G3;

    // gx feed — only q==0 threads consume it
    float w0r = 0.f, w0z = 0.f, w0n = 0.f, c0r = 0.f, c0z = 0.f, c0n = 0.f;
    const float* xs = nullptr;
    const float* gp = nullptr;
    if (layer == 0) {
        w0r = w_ih0[d * G3 + j];
        w0z = w_ih0[d * G3 + 64 + j];
        w0n = w_ih0[d * G3 + 128 + j];
        c0r = b_ih[(size_t)d * G3 + j];
        c0z = b_ih[(size_t)d * G3 + 64 + j];
        c0n = b_ih[(size_t)d * G3 + 128 + j];
        xs = x + (size_t)b * Lseq + t0;
    } else {
        gp = g_gx + (((size_t)d * Bsz + b) * Lseq + t0) * G3 + j;
    }
    float* outp = g_buf + (size_t)b * Lseq * IN2H + d * Hd + j;

    __syncthreads();

    // depth-2 prefetch as STATIC scalars (parity 0 / parity 1)
    float qr0 = 0.f, qz0 = 0.f, qn0 = 0.f;
    float qr1 = 0.f, qz1 = 0.f, qn1 = 0.f;
    if (q == 0) {
        if (layer == 0) {
            qr0 = xs[0];
            qr1 = xs[(long)tstep];
        } else {
            qr0 = gp[0];        qz0 = gp[64];         qn0 = gp[128];
            qr1 = gp[gstep];    qz1 = gp[gstep + 64]; qn1 = gp[gstep + 128];
        }
    }

#define SCAN_STEP(PR, S)                                                      \
    {                                                                         \
        const int s_ = (S);                                                   \
        float rawr = qr##PR, rawz = qz##PR, rawn = qn##PR;                    \
        const int sp_ = s_ + 2;                                               \
        if (q == 0 && sp_ < Lseq) {                                           \
            if (layer == 0) {                                                 \
                qr##PR = xs[(long)sp_ * tstep];                               \
            } else {                                                          \
                qr##PR = gp[(long)sp_ * gstep];                               \
                qz##PR = gp[(long)sp_ * gstep + 64];                          \
                qn##PR = gp[(long)sp_ * gstep + 128];                         \
            }                                                                 \
        }                                                                     \
        const ulonglong2* h4_ =                                               \
            (const ulonglong2*)(h_s[PR] + q * 16);                            \
        ulonglong2 u0 = h4_[0], u1 = h4_[1], u2 = h4_[2], u3 = h4_[3];        \
        ull r0, r1, z0, z1, n0, n1;                                           \
        r0 = fma2(wr[0], u0.x, 0ULL); r1 = fma2(wr[1], u0.y, 0ULL);           \
        z0 = fma2(wz[0], u0.x, 0ULL); z1 = fma2(wz[1], u0.y, 0ULL);           \
        n0 = fma2(wn[0], u0.x, 0ULL); n1 = fma2(wn[1], u0.y, 0ULL);           \
        r0 = fma2(wr[2], u1.x, r0);   r1 = fma2(wr[3], u1.y, r1);             \
        z0 = fma2(wz[2], u1.x, z0);   z1 = fma2(wz[3], u1.y, z1);             \
        n0 = fma2(wn[2], u1.x, n0);   n1 = fma2(wn[3], u1.y, n1);             \
        r0 = fma2(wr[4], u2.x, r0);   r1 = fma2(wr[5], u2.y, r1);             \
        z0 = fma2(wz[4], u2.x, z0);   z1 = fma2(wz[5], u2.y, z1);             \
        n0 = fma2(wn[4], u2.x, n0);   n1 = fma2(wn[5], u2.y, n1);             \
        r0 = fma2(wr[6], u3.x, r0);   r1 = fma2(wr[7], u3.y, r1);             \
        z0 = fma2(wz[6], u3.x, z0);   z1 = fma2(wz[7], u3.y, z1);             \
        n0 = fma2(wn[6], u3.x, n0);   n1 = fma2(wn[7], u3.y, n1);             \
        float2 fr0 = u2f2(r0), fr1 = u2f2(r1);                                \
        float2 fz0 = u2f2(z0), fz1 = u2f2(z1);                                \
        float2 fn0 = u2f2(n0), fn1 = u2f2(n1);                                \
        float pgr = (fr0.x + fr0.y) + (fr1.x + fr1.y);                        \
        float pgz = (fz0.x + fz0.y) + (fz1.x + fz1.y);                        \
        float pgn = (fn0.x + fn0.y) + (fn1.x + fn1.y);                        \
        pgr += __shfl_xor_sync(0xFFFFFFFFu, pgr, 1);                          \
        pgz += __shfl_xor_sync(0xFFFFFFFFu, pgz, 1);                          \
        pgn += __shfl_xor_sync(0xFFFFFFFFu, pgn, 1);                          \
        pgr += __shfl_xor_sync(0xFFFFFFFFu, pgr, 2);                          \
        pgz += __shfl_xor_sync(0xFFFFFFFFu, pgz, 2);                          \
        pgn += __shfl_xor_sync(0xFFFFFFFFu, pgn, 2);                          \
        if (q == 0) {                                                         \
            float gxr, gxz, gxn;                                              \
            if (layer == 0) {                                                 \
                gxr = fmaf(rawr, w0r, c0r);                                   \
                gxz = fmaf(rawr, w0z, c0z);                                   \
                gxn = fmaf(rawr, w0n, c0n);                                   \
            } else {                                                          \
                gxr = rawr; gxz = rawz; gxn = rawn;                           \
            }                                                                 \
            float r_ = sigm_fast(gxr + pgr + br);                             \
            float z_ = sigm_fast(gxz + pgz + bz);                             \
            float n_ = tanh_fast(fmaf(r_, pgn + bn, gxn));                    \
            float hn = fmaf(z_, hreg - n_, n_);                               \
            hreg = hn;                                                        \
            h_s[1 - (PR)][j] = hn;                                            \
            outp[(size_t)(t0 + s_ * tstep) * IN2H] = hn;                      \
        }                                                                     \
        __syncthreads();                                                      \
    }

#pragma unroll 1
    for (int s0 = 0; s0 < Lseq; s0 += 2) {
        SCAN_STEP(0, s0)
        SCAN_STEP(1, s0 + 1)
    }
#undef SCAN_STEP
}

// ---------------- final FC on last timestep ----------------
__global__ void fc_kernel(const float* __restrict__ fc_w,
                          const float* __restrict__ fc_b,
                          float* __restrict__ out) {
    int b = blockIdx.x;
    int c = threadIdx.x;
    __shared__ float last[IN2H];
    if (threadIdx.x < IN2H)
        last[threadIdx.x] =
            g_buf[((size_t)b * Lseq + (Lseq - 1)) * IN2H + threadIdx.x];
    __syncthreads();
    if (c < NCLS) {
        float s = fc_b[c];
        const float* w = fc_w + (size_t)c * IN2H;
#pragma unroll 8
        for (int k = 0; k < IN2H; k++) s += last[k] * w[k];
        out[(size_t)b * NCLS + c] = s;
    }
}

extern "C" void kernel_launch(void* const* d_in, const int* in_sizes, int n_in,
                              void* d_out, int out_size) {
    const float* x     = (const float*)d_in[0];
    const float* w_ih0 = (const float*)d_in[1];
    const float* w_ih  = (const float*)d_in[2];
    const float* w_hh  = (const float*)d_in[3];
    const float* b_ih  = (const float*)d_in[4];
    const float* b_hh  = (const float*)d_in[5];
    const float* fc_w  = (const float*)d_in[6];
    const float* fc_b  = (const float*)d_in[7];
    float* out = (float*)d_out;

    // Layer 0: gx fused into the scan (input size 1)
    scan_kernel<<<dim3(Bsz, 2), 256>>>(w_hh, b_hh, x, w_ih0, b_ih, 0);
    // Layers 1..3: GEMM input projection, then scan
    for (int l = 1; l < 4; l++) {
        gx_gemm_kernel<<<dim3(4, BL / 64), 256>>>(w_ih, b_ih, l);
        scan_kernel<<<dim3(Bsz, 2), 256>>>(w_hh, b_hh, x, w_ih0, b_ih, l);
    }
    fc_kernel<<<Bsz, 256>>>(fc_w, fc_b, out);
}

// round 13
// speedup vs baseline: 1.1611x; 1.1611x over previous
#include <cuda_runtime.h>

#define Bsz   128
#define Lseq  4096
#define Hd    64
#define G3    192
#define IN2H  128
#define NCLS  230
#define BL    (Bsz * Lseq)
#define RD    8          // gx ring depth (steps)

typedef unsigned long long ull;

// Scratch (allocation-free rule: __device__ globals)
__device__ float g_gx[(size_t)2 * BL * G3];    // [dir][b][t][192]  (~805 MB)
__device__ float g_buf[(size_t)BL * IN2H];     // [b][t][128]       (~268 MB)

// ---------------- packed f32x2 / fast-math helpers ----------------
__device__ __forceinline__ ull fma2(ull a, ull b, ull c) {
    ull d;
    asm("fma.rn.f32x2 %0, %1, %2, %3;" : "=l"(d) : "l"(a), "l"(b), "l"(c));
    return d;
}
__device__ __forceinline__ float2 u2f2(ull v) {
    float2 f;
    asm("mov.b64 {%0, %1}, %2;" : "=f"(f.x), "=f"(f.y) : "l"(v));
    return f;
}
__device__ __forceinline__ float tanh_fast(float x) {
    float y;
    asm("tanh.approx.f32 %0, %1;" : "=f"(y) : "f"(x));
    return y;
}
__device__ __forceinline__ float sigm_fast(float x) {
    return fmaf(0.5f, tanh_fast(0.5f * x), 0.5f);
}
__device__ __forceinline__ unsigned smem_u32(const void* p) {
    return (unsigned)__cvta_generic_to_shared(p);
}
__device__ __forceinline__ void cp_async4(unsigned dst, const void* src) {
    asm volatile("cp.async.ca.shared.global [%0], [%1], 4;"
                 :: "r"(dst), "l"(src));
}
__device__ __forceinline__ void cp_async8(unsigned dst, const void* src) {
    asm volatile("cp.async.ca.shared.global [%0], [%1], 8;"
                 :: "r"(dst), "l"(src));
}
__device__ __forceinline__ void cp_async16(unsigned dst, const void* src) {
    asm volatile("cp.async.cg.shared.global [%0], [%1], 16;"
                 :: "r"(dst), "l"(src));
}
__device__ __forceinline__ void cp_commit() {
    asm volatile("cp.async.commit_group;");
}
template <int N>
__device__ __forceinline__ void cp_wait() {
    asm volatile("cp.async.wait_group %0;" :: "n"(N));
}

// ---------------- gx GEMM for layers 1..3 (frozen R7 version) -------------
__global__ void __launch_bounds__(256, 2)
gx_gemm_kernel(const float* __restrict__ w_ih,
               const float* __restrict__ b_ih,
               int layer) {
    const int d  = blockIdx.x & 1;
    const int c0 = (blockIdx.x >> 1) * 96;       // column half
    const size_t row0 = (size_t)blockIdx.y * 64;
    const int tid = threadIdx.x;
    const int tx = tid & 15;   // cols c0 + tx + 16*j, j<6
    const int ty = tid >> 4;   // rows ty + 16*i, i<4

    const ull* inp2 = (const ull*)g_buf;  // 64 ull per row
    const ull* w2g =
        (const ull*)(w_ih + ((size_t)(layer - 1) * 2 + d) * G3 * IN2H);

    __shared__ ull a_s[2][16][65];   // [buf][kpair][row]
    __shared__ ull b_s[2][16][97];   // [buf][kpair][col]
    const unsigned A_BUF_BYTES = 16 * 65 * 8;
    const unsigned B_BUF_BYTES = 16 * 97 * 8;

    unsigned a_dst[4], b_dst[6];
    const ull* a_src[4];
    const ull* b_src[6];
#pragma unroll
    for (int it = 0; it < 4; it++) {
        int lin = tid + it * 256;
        int r = lin >> 4, c2 = lin & 15;
        a_dst[it] = smem_u32(&a_s[0][c2][r]);
        a_src[it] = inp2 + (row0 + r) * 64 + c2;
    }
#pragma unroll
    for (int it = 0; it < 6; it++) {
        int lin = tid + it * 256;
        int cc = lin >> 4, c2 = lin & 15;
        b_dst[it] = smem_u32(&b_s[0][c2][cc]);
        b_src[it] = w2g + (size_t)(c0 + cc) * 64 + c2;
    }

    ull acc[4][6];
#pragma unroll
    for (int i = 0; i < 4; i++)
#pragma unroll
        for (int j = 0; j < 6; j++) acc[i][j] = 0ULL;

#pragma unroll
    for (int it = 0; it < 4; it++) cp_async8(a_dst[it], a_src[it]);
#pragma unroll
    for (int it = 0; it < 6; it++) cp_async8(b_dst[it], b_src[it]);
    cp_commit();

#pragma unroll
    for (int ch = 0; ch < 4; ch++) {
        const int buf = ch & 1;
        if (ch < 3) {
            const int nb = (ch + 1) & 1;
#pragma unroll
            for (int it = 0; it < 4; it++)
                cp_async8(a_dst[it] + nb * A_BUF_BYTES,
                          a_src[it] + (ch + 1) * 16);
#pragma unroll
            for (int it = 0; it < 6; it++)
                cp_async8(b_dst[it] + nb * B_BUF_BYTES,
                          b_src[it] + (ch + 1) * 16);
            cp_commit();
            cp_wait<1>();
        } else {
            cp_wait<0>();
        }
        __syncthreads();
#pragma unroll
        for (int kp = 0; kp < 16; kp++) {
            ull a2[4], b2[6];
#pragma unroll
            for (int i = 0; i < 4; i++) a2[i] = a_s[buf][kp][ty + 16 * i];
#pragma unroll
            for (int j = 0; j < 6; j++) b2[j] = b_s[buf][kp][tx + 16 * j];
#pragma unroll
            for (int i = 0; i < 4; i++)
#pragma unroll
                for (int j = 0; j < 6; j++)
                    acc[i][j] = fma2(a2[i], b2[j], acc[i][j]);
        }
        __syncthreads();
    }

    const float* bih = b_ih + ((size_t)layer * 2 + d) * G3;
#pragma unroll
    for (int i = 0; i < 4; i++) {
        size_t row = row0 + ty + 16 * i;
#pragma unroll
        for (int j = 0; j < 6; j++) {
            int c = c0 + tx + 16 * j;
            float2 f = u2f2(acc[i][j]);
            g_gx[((size_t)d * BL + row) * G3 + c] = f.x + f.y + bih[c];
        }
    }
}

// ---------------- sequential GRU scan (R11 core + cp.async gx ring) -------
// One block per batch element, 256 threads = two independent 128-thread
// direction groups (named barriers). tid = d*128 + j*2 + half:
//   j = component 0..63, half = 32-wide k-half of the dot products.
// Each thread computes all three gate dots (r,z,n) for component j over its
// k-half (weights 3x16 ull = 96 regs); halves combine via shfl_xor(1).
// gx is staged through an 8-step shared-memory ring filled with cp.async
// (one commit group per step, wait_group<6> -> ~6-step latency margin).
// All dynamic indexing (ring slot, h ping-pong parity) targets SMEM, so no
// register array ever gets a dynamic index (the R10 local-memory trap).
__global__ void __launch_bounds__(256)
scan_kernel(const float* __restrict__ w_hh,
            const float* __restrict__ b_hh,
            const float* __restrict__ x,
            const float* __restrict__ w_ih0,
            const float* __restrict__ b_ih,
            int layer) {
    const int b = blockIdx.x;
    const int tid = threadIdx.x;
    const int d = tid >> 7;            // direction
    const int lt = tid & 127;          // lane within direction group
    const int j = lt >> 1;             // component
    const int half = lt & 1;           // k-half
    const unsigned barid = 1 + d;

    const size_t base = ((size_t)layer * 2 + d) * G3;
    const ull* Wr = (const ull*)w_hh + (base + j) * 32 + half * 16;
    const ull* Wz = (const ull*)w_hh + (base + 64 + j) * 32 + half * 16;
    const ull* Wn = (const ull*)w_hh + (base + 128 + j) * 32 + half * 16;
    ull wr[16], wz[16], wn[16];
#pragma unroll
    for (int i = 0; i < 16; i++) { wr[i] = Wr[i]; wz[i] = Wz[i]; wn[i] = Wn[i]; }
    const float br = b_hh[base + j];
    const float bz = b_hh[base + 64 + j];
    const float bn = b_hh[base + 128 + j];

    __shared__ __align__(16) float h_s[2][2][Hd];      // [dir][parity][comp]
    __shared__ __align__(16) float ring[2][RD][G3];    // gx staging ring
    if (lt < Hd) h_s[d][0][lt] = 0.0f;
    float hreg = 0.0f;  // previous h[j], maintained on half==0

    const int t0 = (d == 0) ? 0 : (Lseq - 1);
    const int tstep = (d == 0) ? 1 : -1;

    // gate-input source
    const float* src;
    if (layer == 0) src = x + (size_t)b * Lseq + t0;
    else            src = g_gx + (((size_t)d * Bsz + b) * Lseq + t0) * G3;

    float w0r = 0.f, w0z = 0.f, w0n = 0.f, c0r = 0.f, c0z = 0.f, c0n = 0.f;
    if (layer == 0 && half == 0) {
        w0r = w_ih0[d * G3 + j];
        w0z = w_ih0[d * G3 + 64 + j];
        w0n = w_ih0[d * G3 + 128 + j];
        c0r = b_ih[(size_t)d * G3 + j];
        c0z = b_ih[(size_t)d * G3 + 64 + j];
        c0n = b_ih[(size_t)d * G3 + 128 + j];
    }
    float* outp = g_buf + (size_t)b * Lseq * IN2H + d * Hd + j;

    // ---- ring prologue: fill steps 0..RD-2 (7 commit groups) ----
#pragma unroll
    for (int p = 0; p < RD - 1; p++) {
        if (layer == 0) {
            if (lt == 0)
                cp_async4(smem_u32(&ring[d][p][0]), src + (long)p * tstep);
        } else if (lt < 48) {
            cp_async16(smem_u32(&ring[d][p][lt * 4]),
                       src + (long)p * tstep * G3 + lt * 4);
        }
        cp_commit();
    }
    cp_wait<RD - 2>();   // step-0 slot complete
    asm volatile("bar.sync %0, %1;" :: "r"(barid), "r"(128) : "memory");

#pragma unroll 1
    for (int s = 0; s < Lseq; s++) {
        const int slot = s & (RD - 1);
        const int pr = s & 1;

        // refill slot for step s+RD-1 (that slot was last read at step s-1,
        // behind a barrier -> no race with this step's readers)
        const int sf = s + RD - 1;
        if (sf < Lseq) {
            if (layer == 0) {
                if (lt == 0)
                    cp_async4(smem_u32(&ring[d][sf & (RD - 1)][0]),
                              src + (long)sf * tstep);
            } else if (lt < 48) {
                cp_async16(smem_u32(&ring[d][sf & (RD - 1)][lt * 4]),
                           src + (long)sf * tstep * G3 + lt * 4);
            }
        }
        cp_commit();

        // half-dots for r,z,n over this thread's 32 h-components
        const ulonglong2* h4 =
            (const ulonglong2*)(h_s[d][pr] + half * 32);
        ull r0 = 0, r1 = 0, z0 = 0, z1 = 0, n0 = 0, n1 = 0;
#pragma unroll
        for (int i = 0; i < 4; i++) {
            ulonglong2 u = h4[2 * i];
            ulonglong2 v = h4[2 * i + 1];
            r0 = fma2(wr[4 * i + 0], u.x, r0);
            r1 = fma2(wr[4 * i + 1], u.y, r1);
            z0 = fma2(wz[4 * i + 0], u.x, z0);
            z1 = fma2(wz[4 * i + 1], u.y, z1);
            n0 = fma2(wn[4 * i + 0], u.x, n0);
            n1 = fma2(wn[4 * i + 1], u.y, n1);
            r0 = fma2(wr[4 * i + 2], v.x, r0);
            r1 = fma2(wr[4 * i + 3], v.y, r1);
            z0 = fma2(wz[4 * i + 2], v.x, z0);
            z1 = fma2(wz[4 * i + 3], v.y, z1);
            n0 = fma2(wn[4 * i + 2], v.x, n0);
            n1 = fma2(wn[4 * i + 3], v.y, n1);
        }
        float2 fr0 = u2f2(r0), fr1 = u2f2(r1);
        float2 fz0 = u2f2(z0), fz1 = u2f2(z1);
        float2 fn0 = u2f2(n0), fn1 = u2f2(n1);
        float pgr = (fr0.x + fr0.y) + (fr1.x + fr1.y);
        float pgz = (fz0.x + fz0.y) + (fz1.x + fz1.y);
        float pgn = (fn0.x + fn0.y) + (fn1.x + fn1.y);

        pgr += __shfl_xor_sync(0xFFFFFFFFu, pgr, 1);
        pgz += __shfl_xor_sync(0xFFFFFFFFu, pgz, 1);
        pgn += __shfl_xor_sync(0xFFFFFFFFu, pgn, 1);

        if (half == 0) {
            float gxr, gxz, gxn;
            if (layer == 0) {
                float xv = ring[d][slot][0];
                gxr = fmaf(xv, w0r, c0r);
                gxz = fmaf(xv, w0z, c0z);
                gxn = fmaf(xv, w0n, c0n);
            } else {
                gxr = ring[d][slot][j];
                gxz = ring[d][slot][64 + j];
                gxn = ring[d][slot][128 + j];
            }
            float r_ = sigm_fast(gxr + pgr + br);
            float z_ = sigm_fast(gxz + pgz + bz);
            float n_ = tanh_fast(fmaf(r_, pgn + bn, gxn));
            float hn = fmaf(z_, hreg - n_, n_);   // (1-z)*n + z*h
            hreg = hn;
            h_s[d][pr ^ 1][j] = hn;
            outp[(size_t)(t0 + s * tstep) * IN2H] = hn;
        }
        cp_wait<RD - 2>();   // step s+1's group retired
        asm volatile("bar.sync %0, %1;" :: "r"(barid), "r"(128) : "memory");
    }
}

// ---------------- final FC on last timestep ----------------
__global__ void fc_kernel(const float* __restrict__ fc_w,
                          const float* __restrict__ fc_b,
                          float* __restrict__ out) {
    int b = blockIdx.x;
    int c = threadIdx.x;
    __shared__ float last[IN2H];
    if (threadIdx.x < IN2H)
        last[threadIdx.x] =
            g_buf[((size_t)b * Lseq + (Lseq - 1)) * IN2H + threadIdx.x];
    __syncthreads();
    if (c < NCLS) {
        float s = fc_b[c];
        const float* w = fc_w + (size_t)c * IN2H;
#pragma unroll 8
        for (int k = 0; k < IN2H; k++) s += last[k] * w[k];
        out[(size_t)b * NCLS + c] = s;
    }
}

extern "C" void kernel_launch(void* const* d_in, const int* in_sizes, int n_in,
                              void* d_out, int out_size) {
    const float* x     = (const float*)d_in[0];
    const float* w_ih0 = (const float*)d_in[1];
    const float* w_ih  = (const float*)d_in[2];
    const float* w_hh  = (const float*)d_in[3];
    const float* b_ih  = (const float*)d_in[4];
    const float* b_hh  = (const float*)d_in[5];
    const float* fc_w  = (const float*)d_in[6];
    const float* fc_b  = (const float*)d_in[7];
    float* out = (float*)d_out;

    // Layer 0: gx fused into the scan (input size 1)
    scan_kernel<<<Bsz, 256>>>(w_hh, b_hh, x, w_ih0, b_ih, 0);
    // Layers 1..3: GEMM input projection, then scan
    for (int l = 1; l < 4; l++) {
        gx_gemm_kernel<<<dim3(4, BL / 64), 256>>>(w_ih, b_ih, l);
        scan_kernel<<<Bsz, 256>>>(w_hh, b_hh, x, w_ih0, b_ih, l);
    }
    fc_kernel<<<Bsz, 256>>>(fc_w, fc_b, out);
}

// round 14
// speedup vs baseline: 1.2258x; 1.0557x over previous
#include <cuda_runtime.h>

#define Bsz   128
#define Lseq  4096
#define Hd    64
#define G3    192
#define IN2H  128
#define NCLS  230
#define BL    (Bsz * Lseq)

typedef unsigned long long ull;

// Scratch (allocation-free rule: __device__ globals)
__device__ float g_gx[(size_t)2 * BL * G3];    // [dir][b][t][192]  (~805 MB)
__device__ float g_buf[(size_t)BL * IN2H];     // [b][t][128]       (~268 MB)

// ---------------- packed f32x2 / fast-math helpers ----------------
__device__ __forceinline__ ull fma2(ull a, ull b, ull c) {
    ull d;
    asm("fma.rn.f32x2 %0, %1, %2, %3;" : "=l"(d) : "l"(a), "l"(b), "l"(c));
    return d;
}
__device__ __forceinline__ float2 u2f2(ull v) {
    float2 f;
    asm("mov.b64 {%0, %1}, %2;" : "=f"(f.x), "=f"(f.y) : "l"(v));
    return f;
}
__device__ __forceinline__ float tanh_fast(float x) {
    float y;
    asm("tanh.approx.f32 %0, %1;" : "=f"(y) : "f"(x));
    return y;
}
__device__ __forceinline__ float sigm_fast(float x) {
    return fmaf(0.5f, tanh_fast(0.5f * x), 0.5f);
}
__device__ __forceinline__ unsigned smem_u32(const void* p) {
    return (unsigned)__cvta_generic_to_shared(p);
}
__device__ __forceinline__ void cp_async16(unsigned dst, const void* src) {
    asm volatile("cp.async.cg.shared.global [%0], [%1], 16;"
                 :: "r"(dst), "l"(src));
}
__device__ __forceinline__ void cp_commit() {
    asm volatile("cp.async.commit_group;");
}
template <int N>
__device__ __forceinline__ void cp_wait() {
    asm volatile("cp.async.wait_group %0;" :: "n"(N));
}

// ---------------- gx GEMM for layers 1..3 ----------------
// Tile 64 rows x 96 cols, K=128 in 4 chunks of 16 k-pairs.
// SMEM layout [row][kpair] (pad 18 ull = 144B, 16B-aligned) so operands load
// as LDS.128 (2 k-pairs per load): per 2 k-pairs = 10 LDS.128 + 48 fma2.
__global__ void __launch_bounds__(256, 2)
gx_gemm_kernel(const float* __restrict__ w_ih,
               const float* __restrict__ b_ih,
               int layer) {
    const int d  = blockIdx.x & 1;
    const int c0 = (blockIdx.x >> 1) * 96;       // column half
    const size_t row0 = (size_t)blockIdx.y * 64;
    const int tid = threadIdx.x;
    const int tx = tid & 15;   // cols c0 + tx + 16*j, j<6
    const int ty = tid >> 4;   // rows ty + 16*i, i<4

    const ull* inp2 = (const ull*)g_buf;  // 64 ull per row
    const ull* w2g =
        (const ull*)(w_ih + ((size_t)(layer - 1) * 2 + d) * G3 * IN2H);

    __shared__ __align__(16) ull a_s[2][64][18];   // [buf][row][kpair(+pad)]
    __shared__ __align__(16) ull b_s[2][96][18];   // [buf][col][kpair(+pad)]

    // per-thread cp.async slots (A: 2 x 16B, B: 3 x 16B per chunk)
    // A: lin in [0,512): r = lin>>3, pp = lin&7 (pair-of-kpairs)
    // B: lin in [0,768): cc = lin>>3, pp = lin&7
    unsigned a_dst[2], b_dst[3];
    const ull* a_src[2];
    const ull* b_src[3];
#pragma unroll
    for (int it = 0; it < 2; it++) {
        int lin = tid + it * 256;
        int r = lin >> 3, pp = lin & 7;
        a_dst[it] = smem_u32(&a_s[0][r][2 * pp]);
        a_src[it] = inp2 + (row0 + r) * 64 + 2 * pp;
    }
#pragma unroll
    for (int it = 0; it < 3; it++) {
        int lin = tid + it * 256;
        int cc = lin >> 3, pp = lin & 7;
        b_dst[it] = smem_u32(&b_s[0][cc][2 * pp]);
        b_src[it] = w2g + (size_t)(c0 + cc) * 64 + 2 * pp;
    }
    const unsigned A_BUF_BYTES = 64 * 18 * 8;
    const unsigned B_BUF_BYTES = 96 * 18 * 8;

    ull acc[4][6];
#pragma unroll
    for (int i = 0; i < 4; i++)
#pragma unroll
        for (int j = 0; j < 6; j++) acc[i][j] = 0ULL;

    // prologue: chunk 0 -> buf 0   (chunk ch covers kpairs ch*16..ch*16+15)
#pragma unroll
    for (int it = 0; it < 2; it++) cp_async16(a_dst[it], a_src[it]);
#pragma unroll
    for (int it = 0; it < 3; it++) cp_async16(b_dst[it], b_src[it]);
    cp_commit();

#pragma unroll
    for (int ch = 0; ch < 4; ch++) {
        const int buf = ch & 1;
        if (ch < 3) {
            const int nb = (ch + 1) & 1;
#pragma unroll
            for (int it = 0; it < 2; it++)
                cp_async16(a_dst[it] + nb * A_BUF_BYTES,
                           a_src[it] + (ch + 1) * 16);
#pragma unroll
            for (int it = 0; it < 3; it++)
                cp_async16(b_dst[it] + nb * B_BUF_BYTES,
                           b_src[it] + (ch + 1) * 16);
            cp_commit();
            cp_wait<1>();
        } else {
            cp_wait<0>();
        }
        __syncthreads();
#pragma unroll
        for (int kp2 = 0; kp2 < 8; kp2++) {   // 2 k-pairs per iteration
            ulonglong2 av[4], bv[6];
#pragma unroll
            for (int i = 0; i < 4; i++)
                av[i] = *(const ulonglong2*)&a_s[buf][ty + 16 * i][2 * kp2];
#pragma unroll
            for (int j = 0; j < 6; j++)
                bv[j] = *(const ulonglong2*)&b_s[buf][tx + 16 * j][2 * kp2];
#pragma unroll
            for (int i = 0; i < 4; i++)
#pragma unroll
                for (int j = 0; j < 6; j++) {
                    acc[i][j] = fma2(av[i].x, bv[j].x, acc[i][j]);
                    acc[i][j] = fma2(av[i].y, bv[j].y, acc[i][j]);
                }
        }
        __syncthreads();
    }

    const float* bih = b_ih + ((size_t)layer * 2 + d) * G3;
#pragma unroll
    for (int i = 0; i < 4; i++) {
        size_t row = row0 + ty + 16 * i;
#pragma unroll
        for (int j = 0; j < 6; j++) {
            int c = c0 + tx + 16 * j;
            float2 f = u2f2(acc[i][j]);
            g_gx[((size_t)d * BL + row) * G3 + c] = f.x + f.y + bih[c];
        }
    }
}

// ---------------- sequential GRU scan (R11 anchor, verbatim) --------------
// One block per batch element, 256 threads. tid = d*128 + j*2 + half.
// Split-k=2 + shfl_xor(1), ping-pong h, one 128-thread named barrier/step,
// step loop unrolled x2 so parity & prefetch scalars are compile-time.
__global__ void __launch_bounds__(256)
scan_kernel(const float* __restrict__ w_hh,
            const float* __restrict__ b_hh,
            const float* __restrict__ x,
            const float* __restrict__ w_ih0,
            const float* __restrict__ b_ih,
            int layer) {
    const int b = blockIdx.x;
    const int tid = threadIdx.x;
    const int d = tid >> 7;            // direction
    const int j = (tid & 127) >> 1;    // component
    const int half = tid & 1;          // k-half
    const unsigned barid = 1 + d;

    const size_t base = ((size_t)layer * 2 + d) * G3;
    const ull* Wr = (const ull*)w_hh + (base + j) * 32 + half * 16;
    const ull* Wz = (const ull*)w_hh + (base + 64 + j) * 32 + half * 16;
    const ull* Wn = (const ull*)w_hh + (base + 128 + j) * 32 + half * 16;
    ull wr[16], wz[16], wn[16];
#pragma unroll
    for (int i = 0; i < 16; i++) { wr[i] = Wr[i]; wz[i] = Wz[i]; wn[i] = Wn[i]; }
    const float br = b_hh[base + j];
    const float bz = b_hh[base + 64 + j];
    const float bn = b_hh[base + 128 + j];

    __shared__ __align__(16) float h_s[2][2][Hd];  // [dir][parity][comp]
    if ((tid & 127) < Hd) h_s[d][0][tid & 127] = 0.0f;
    float hreg = 0.0f;  // previous h[j], maintained on half==0

    const int t0 = (d == 0) ? 0 : (Lseq - 1);
    const int tstep = (d == 0) ? 1 : -1;
    const long gstep = (long)tstep * G3;

    // gx feed — only half==0 threads consume it
    float w0r = 0.f, w0z = 0.f, w0n = 0.f, c0r = 0.f, c0z = 0.f, c0n = 0.f;
    const float* xs = nullptr;
    const float* gp = nullptr;
    if (layer == 0) {
        w0r = w_ih0[d * G3 + j];
        w0z = w_ih0[d * G3 + 64 + j];
        w0n = w_ih0[d * G3 + 128 + j];
        c0r = b_ih[(size_t)d * G3 + j];
        c0z = b_ih[(size_t)d * G3 + 64 + j];
        c0n = b_ih[(size_t)d * G3 + 128 + j];
        xs = x + (size_t)b * Lseq + t0;
    } else {
        gp = g_gx + (((size_t)d * Bsz + b) * Lseq + t0) * G3 + j;
    }
    float* outp = g_buf + (size_t)b * Lseq * IN2H + d * Hd + j;

    asm volatile("bar.sync %0, %1;" :: "r"(barid), "r"(128) : "memory");

    // depth-2 prefetch as STATIC scalars (parity 0 / parity 1)
    float qr0 = 0.f, qz0 = 0.f, qn0 = 0.f;
    float qr1 = 0.f, qz1 = 0.f, qn1 = 0.f;
    if (half == 0) {
        if (layer == 0) {
            qr0 = xs[0];
            qr1 = xs[(long)tstep];
        } else {
            qr0 = gp[0];        qz0 = gp[64];         qn0 = gp[128];
            qr1 = gp[gstep];    qz1 = gp[gstep + 64]; qn1 = gp[gstep + 128];
        }
    }

#define SCAN_STEP(PR, S)                                                      \
    {                                                                         \
        const int s_ = (S);                                                   \
        float rawr = qr##PR, rawz = qz##PR, rawn = qn##PR;                    \
        const int sp_ = s_ + 2;                                               \
        if (half == 0 && sp_ < Lseq) {                                        \
            if (layer == 0) {                                                 \
                qr##PR = xs[(long)sp_ * tstep];                               \
            } else {                                                          \
                qr##PR = gp[(long)sp_ * gstep];                               \
                qz##PR = gp[(long)sp_ * gstep + 64];                          \
                qn##PR = gp[(long)sp_ * gstep + 128];                         \
            }                                                                 \
        }                                                                     \
        const ulonglong2* h4_ =                                               \
            (const ulonglong2*)(h_s[d][PR] + half * 32);                      \
        ull r0 = 0, r1 = 0, z0 = 0, z1 = 0, n0 = 0, n1 = 0;                   \
        _Pragma("unroll")                                                     \
        for (int i = 0; i < 4; i++) {                                         \
            ulonglong2 u = h4_[2 * i];                                        \
            ulonglong2 v = h4_[2 * i + 1];                                    \
            r0 = fma2(wr[4 * i + 0], u.x, r0);                                \
            r1 = fma2(wr[4 * i + 1], u.y, r1);                                \
            z0 = fma2(wz[4 * i + 0], u.x, z0);                                \
            z1 = fma2(wz[4 * i + 1], u.y, z1);                                \
            n0 = fma2(wn[4 * i + 0], u.x, n0);                                \
            n1 = fma2(wn[4 * i + 1], u.y, n1);                                \
            r0 = fma2(wr[4 * i + 2], v.x, r0);                                \
            r1 = fma2(wr[4 * i + 3], v.y, r1);                                \
            z0 = fma2(wz[4 * i + 2], v.x, z0);                                \
            z1 = fma2(wz[4 * i + 3], v.y, z1);                                \
            n0 = fma2(wn[4 * i + 2], v.x, n0);                                \
            n1 = fma2(wn[4 * i + 3], v.y, n1);                                \
        }                                                                     \
        float2 fr0 = u2f2(r0), fr1 = u2f2(r1);                                \
        float2 fz0 = u2f2(z0), fz1 = u2f2(z1);                                \
        float2 fn0 = u2f2(n0), fn1 = u2f2(n1);                                \
        float pgr = (fr0.x + fr0.y) + (fr1.x + fr1.y);                        \
        float pgz = (fz0.x + fz0.y) + (fz1.x + fz1.y);                        \
        float pgn = (fn0.x + fn0.y) + (fn1.x + fn1.y);                        \
        pgr += __shfl_xor_sync(0xFFFFFFFFu, pgr, 1);                          \
        pgz += __shfl_xor_sync(0xFFFFFFFFu, pgz, 1);                          \
        pgn += __shfl_xor_sync(0xFFFFFFFFu, pgn, 1);                          \
        if (half == 0) {                                                      \
            float gxr, gxz, gxn;                                              \
            if (layer == 0) {                                                 \
                gxr = fmaf(rawr, w0r, c0r);                                   \
                gxz = fmaf(rawr, w0z, c0z);                                   \
                gxn = fmaf(rawr, w0n, c0n);                                   \
            } else {                                                          \
                gxr = rawr; gxz = rawz; gxn = rawn;                           \
            }                                                                 \
            float r_ = sigm_fast(gxr + pgr + br);                             \
            float z_ = sigm_fast(gxz + pgz + bz);                             \
            float n_ = tanh_fast(fmaf(r_, pgn + bn, gxn));                    \
            float hn = fmaf(z_, hreg - n_, n_);                               \
            hreg = hn;                                                        \
            h_s[d][1 - (PR)][j] = hn;                                         \
            outp[(size_t)(t0 + s_ * tstep) * IN2H] = hn;                      \
        }                                                                     \
        asm volatile("bar.sync %0, %1;" :: "r"(barid), "r"(128) : "memory");  \
    }

#pragma unroll 1
    for (int s0 = 0; s0 < Lseq; s0 += 2) {
        SCAN_STEP(0, s0)
        SCAN_STEP(1, s0 + 1)
    }
#undef SCAN_STEP
}

// ---------------- final FC on last timestep ----------------
__global__ void fc_kernel(const float* __restrict__ fc_w,
                          const float* __restrict__ fc_b,
                          float* __restrict__ out) {
    int b = blockIdx.x;
    int c = threadIdx.x;
    __shared__ float last[IN2H];
    if (threadIdx.x < IN2H)
        last[threadIdx.x] =
            g_buf[((size_t)b * Lseq + (Lseq - 1)) * IN2H + threadIdx.x];
    __syncthreads();
    if (c < NCLS) {
        float s = fc_b[c];
        const float* w = fc_w + (size_t)c * IN2H;
#pragma unroll 8
        for (int k = 0; k < IN2H; k++) s += last[k] * w[k];
        out[(size_t)b * NCLS + c] = s;
    }
}

extern "C" void kernel_launch(void* const* d_in, const int* in_sizes, int n_in,
                              void* d_out, int out_size) {
    const float* x     = (const float*)d_in[0];
    const float* w_ih0 = (const float*)d_in[1];
    const float* w_ih  = (const float*)d_in[2];
    const float* w_hh  = (const float*)d_in[3];
    const float* b_ih  = (const float*)d_in[4];
    const float* b_hh  = (const float*)d_in[5];
    const float* fc_w  = (const float*)d_in[6];
    const float* fc_b  = (const float*)d_in[7];
    float* out = (float*)d_out;

    // Layer 0: gx fused into the scan (input size 1)
    scan_kernel<<<Bsz, 256>>>(w_hh, b_hh, x, w_ih0, b_ih, 0);
    // Layers 1..3: GEMM input projection, then scan
    for (int l = 1; l < 4; l++) {
        gx_gemm_kernel<<<dim3(4, BL / 64), 256>>>(w_ih, b_ih, l);
        scan_kernel<<<Bsz, 256>>>(w_hh, b_hh, x, w_ih0, b_ih, l);
    }
    fc_kernel<<<Bsz, 256>>>(fc_w, fc_b, out);
}